// round 1
// baseline (speedup 1.0000x reference)
#include <cuda_runtime.h>

#define R_BINS 64
#define Z_BINS 64
#define NBINS (R_BINS * Z_BINS)

__device__ float g_hist[NBINS];

static __device__ __forceinline__ void bin_point(float* sh, float x, float y, float z, float m) {
    const float DRf = 0.15625f;      // (10-0)/64, exact in fp32
    const float Z_MINf = -2.0f;
    const float INV_DZ = 16.0f;      // 1/0.0625, exact in fp32
    float r = sqrtf(x * x + y * y);
    // Match reference IEEE division: floor(r / DR). 1/DR = 6.4 is inexact,
    // so use a real division to keep boundary points in the same bin as jnp.
    int i = (int)floorf(__fdiv_rn(r, DRf));
    int j = (int)floorf((z - Z_MINf) * INV_DZ);
    if (i >= 0 && i < R_BINS && j >= 0 && j < Z_BINS) {
        atomicAdd(sh + (i << 6) + j, m);
    }
}

__global__ void zero_kernel() {
    int idx = blockIdx.x * blockDim.x + threadIdx.x;
    if (idx < NBINS) g_hist[idx] = 0.0f;
}

__global__ void hist_kernel(const float4* __restrict__ pos4,
                            const float4* __restrict__ mass4,
                            int ngroups) {
    __shared__ float sh[NBINS];
    for (int i = threadIdx.x; i < NBINS; i += blockDim.x) sh[i] = 0.0f;
    __syncthreads();

    const int stride = gridDim.x * blockDim.x;
    for (int g = blockIdx.x * blockDim.x + threadIdx.x; g < ngroups; g += stride) {
        // 4 points = 12 floats = 3 coalesced float4 loads + 1 float4 of masses
        float4 a = pos4[3 * g + 0];
        float4 b = pos4[3 * g + 1];
        float4 c = pos4[3 * g + 2];
        float4 m = mass4[g];
        bin_point(sh, a.x, a.y, a.z, m.x);
        bin_point(sh, a.w, b.x, b.y, m.y);
        bin_point(sh, b.z, b.w, c.x, m.z);
        bin_point(sh, c.y, c.z, c.w, m.w);
    }

    __syncthreads();
    for (int i = threadIdx.x; i < NBINS; i += blockDim.x) {
        float v = sh[i];
        if (v != 0.0f) atomicAdd(&g_hist[i], v);
    }
}

__global__ void finalize_kernel(float* __restrict__ out) {
    int idx = blockIdx.x * blockDim.x + threadIdx.x;
    if (idx >= NBINS) return;
    const float DRf = 0.15625f;
    const float DZf = 0.0625f;
    const float PIf = 3.14159265358979f; // rounds to fp32 pi, matches math.pi -> f32
    int i = idx >> 6;
    float r0 = (float)i * DRf;
    float r1 = (float)(i + 1) * DRf;
    float vol = PIf * (r1 * r1 - r0 * r0) * DZf;
    out[idx] = g_hist[idx] / vol;
}

extern "C" void kernel_launch(void* const* d_in, const int* in_sizes, int n_in,
                              void* d_out, int out_size) {
    const float4* pos4 = (const float4*)d_in[0];   // positions [N,3] float32
    const float4* mass4 = (const float4*)d_in[1];  // masses [N] float32
    int n = in_sizes[1];                           // N points
    int ngroups = n / 4;                           // N is 2^24, divisible by 4

    zero_kernel<<<(NBINS + 255) / 256, 256>>>();

    const int threads = 512;
    const int blocks = 148 * 4;                    // persistent-ish grid, grid-stride loop
    hist_kernel<<<blocks, threads>>>(pos4, mass4, ngroups);

    finalize_kernel<<<(NBINS + 255) / 256, 256>>>((float*)d_out);
}

// round 2
// speedup vs baseline: 1.1900x; 1.1900x over previous
#include <cuda_runtime.h>

#define R_BINS 64
#define Z_BINS 64
#define NBINS (R_BINS * Z_BINS)
#define NBLOCKS (148 * 4)
#define NTHREADS 512

__device__ float g_hist[NBINS];          // zero-initialized at module load; kernel leaves it zeroed
__device__ unsigned int g_ticket;        // zero-initialized; kernel resets it each launch

static __device__ __forceinline__ void bin_point(float* sh, float x, float y, float z, float m) {
    const float DRf = 0.15625f;          // exact in fp32
    const float INV_DR = 6.4f;           // inexact; fixed up against exact edges below
    const float Z_MINf = -2.0f;
    const float INV_DZ = 16.0f;          // exact (1/0.0625) -> multiply == reference's divide
    float r = sqrtf(x * x + y * y);
    int i = (int)(r * INV_DR);           // r >= 0, truncation == floor
    // Exact-edge fixup: bin edges i*DR are exactly representable.
    if (r < (float)i * DRf) --i;
    else if (r >= (float)(i + 1) * DRf) ++i;
    int j = (int)floorf((z - Z_MINf) * INV_DZ);
    if (i >= 0 && i < R_BINS && j >= 0 && j < Z_BINS) {
        atomicAdd(sh + (i << 6) + j, m);
    }
}

__global__ void __launch_bounds__(NTHREADS, 4)
fused_hist_kernel(const float4* __restrict__ pos4,
                  const float4* __restrict__ mass4,
                  int ngroups,
                  float* __restrict__ out) {
    __shared__ float sh[NBINS];
    __shared__ int s_is_last;
    for (int i = threadIdx.x; i < NBINS; i += NTHREADS) sh[i] = 0.0f;
    __syncthreads();

    const int stride = gridDim.x * NTHREADS;
    for (int g = blockIdx.x * NTHREADS + threadIdx.x; g < ngroups; g += stride) {
        // 4 points = 12 floats = 3 coalesced float4 loads + 1 float4 of masses
        float4 a = pos4[3 * g + 0];
        float4 b = pos4[3 * g + 1];
        float4 c = pos4[3 * g + 2];
        float4 m = mass4[g];
        bin_point(sh, a.x, a.y, a.z, m.x);
        bin_point(sh, a.w, b.x, b.y, m.y);
        bin_point(sh, b.z, b.w, c.x, m.z);
        bin_point(sh, c.y, c.z, c.w, m.w);
    }

    __syncthreads();
    // Flush per-block partials to the global accumulator.
    for (int i = threadIdx.x; i < NBINS; i += NTHREADS) {
        float v = sh[i];
        if (v != 0.0f) atomicAdd(&g_hist[i], v);
    }

    // Make this block's atomics visible, then take a ticket.
    __threadfence();
    if (threadIdx.x == 0) {
        unsigned int t = atomicAdd(&g_ticket, 1u);
        s_is_last = (t == (unsigned int)(gridDim.x - 1));
    }
    __syncthreads();

    if (s_is_last) {
        // Last block: finalize and reset state for the next (graph-replayed) launch.
        const float DRf = 0.15625f;
        const float DZf = 0.0625f;
        const float PIf = 3.14159265358979f;
        for (int idx = threadIdx.x; idx < NBINS; idx += NTHREADS) {
            // atomicExch: coherent read of all blocks' contributions AND reset to 0.
            float v = atomicExch(&g_hist[idx], 0.0f);
            int i = idx >> 6;
            float r0 = (float)i * DRf;
            float r1 = (float)(i + 1) * DRf;
            float vol = PIf * (r1 * r1 - r0 * r0) * DZf;
            out[idx] = v / vol;
        }
        if (threadIdx.x == 0) atomicExch(&g_ticket, 0u);
    }
}

extern "C" void kernel_launch(void* const* d_in, const int* in_sizes, int n_in,
                              void* d_out, int out_size) {
    const float4* pos4 = (const float4*)d_in[0];   // positions [N,3] float32
    const float4* mass4 = (const float4*)d_in[1];  // masses [N] float32
    int n = in_sizes[1];                           // N points (2^24)
    int ngroups = n / 4;

    fused_hist_kernel<<<NBLOCKS, NTHREADS>>>(pos4, mass4, ngroups, (float*)d_out);
}